// round 1
// baseline (speedup 1.0000x reference)
#include <cuda_runtime.h>
#include <cuda_bf16.h>
#include <math.h>

// Problem constants (fixed by the reference)
#define NNODES 100000
#define NEDGES 1600000
#define DFEAT  128          // D_IN = H*D_HID = H*D_OUT = 128 everywhere
#define HEADS  4
#define DHEAD  32
#define NEG_SLOPE 0.2f

// ---------------- scratch (static device globals; no allocations) ------------
__device__ int   g_deg[NNODES];
__device__ int   g_cursor[NNODES];
__device__ int   g_scan[NNODES];
__device__ int   g_partials[128];
__device__ int   g_off[NNODES + 1];
__device__ int   g_csr[NEDGES];
__device__ float g_bufA[(size_t)NNODES * DFEAT];   // GEMM outputs (pre-aggregation h)
__device__ float g_bufB[(size_t)NNODES * DFEAT];   // layer-1 aggregated + relu
__device__ float g_es[NNODES * HEADS];
__device__ float g_ed[NNODES * HEADS];

// ---------------- CSR build --------------------------------------------------
__global__ void zero_kernel(int n) {
    int i = blockIdx.x * blockDim.x + threadIdx.x;
    if (i < n) { g_deg[i] = 0; g_cursor[i] = 0; }
}

__global__ void count_kernel(const int* __restrict__ dst, int e) {
    int i = blockIdx.x * blockDim.x + threadIdx.x;
    if (i < e) atomicAdd(&g_deg[dst[i]], 1);
}

// per-block inclusive scan of g_deg into g_scan; block sums into g_partials
__global__ void scan1_kernel(int n) {
    __shared__ int sh[1024];
    int i = blockIdx.x * 1024 + threadIdx.x;
    int v = (i < n) ? g_deg[i] : 0;
    sh[threadIdx.x] = v;
    for (int o = 1; o < 1024; o <<= 1) {
        __syncthreads();
        int t = (threadIdx.x >= o) ? sh[threadIdx.x - o] : 0;
        __syncthreads();
        sh[threadIdx.x] += t;
    }
    __syncthreads();
    if (i < n) g_scan[i] = sh[threadIdx.x];
    if (threadIdx.x == 1023) g_partials[blockIdx.x] = sh[1023];
}

// single block: exclusive scan of block partial sums (nb <= 128)
__global__ void scan2_kernel(int nb) {
    __shared__ int sh[128];
    int v = (threadIdx.x < nb) ? g_partials[threadIdx.x] : 0;
    sh[threadIdx.x] = v;
    for (int o = 1; o < 128; o <<= 1) {
        __syncthreads();
        int t = (threadIdx.x >= o) ? sh[threadIdx.x - o] : 0;
        __syncthreads();
        sh[threadIdx.x] += t;
    }
    __syncthreads();
    if (threadIdx.x < nb) g_partials[threadIdx.x] = sh[threadIdx.x] - v;
}

__global__ void scan3_kernel(int n, int e) {
    int i = blockIdx.x * 1024 + threadIdx.x;
    if (i < n) g_off[i] = g_scan[i] - g_deg[i] + g_partials[blockIdx.x];
    if (i == 0) g_off[n] = e;
}

__global__ void scatter_kernel(const int* __restrict__ src,
                               const int* __restrict__ dst, int e) {
    int i = blockIdx.x * blockDim.x + threadIdx.x;
    if (i < e) {
        int d = dst[i];
        int slot = g_off[d] + atomicAdd(&g_cursor[d], 1);
        g_csr[slot] = src[i];
    }
}

// ---------------- GEMM: out[M,128] = X[M,128] @ W[128,128] -------------------
#define GBM 128
#define GBK 16
__global__ __launch_bounds__(256)
void gemm128_kernel(const float* __restrict__ X, const float* __restrict__ W,
                    float* __restrict__ out, int M) {
    __shared__ float Xs[GBK][GBM + 4];
    __shared__ float Ws[GBK][128];
    int tid = threadIdx.x;
    int tx = tid & 15, ty = tid >> 4;
    int rowBase = blockIdx.x * GBM;
    float acc[8][8];
#pragma unroll
    for (int i = 0; i < 8; i++)
#pragma unroll
        for (int j = 0; j < 8; j++) acc[i][j] = 0.f;

    for (int k0 = 0; k0 < 128; k0 += GBK) {
#pragma unroll
        for (int i = 0; i < 2; i++) {
            int r  = (tid >> 2) + i * 64;
            int c4 = (tid & 3) * 4;
            int gr = rowBase + r;
            float4 v = make_float4(0.f, 0.f, 0.f, 0.f);
            if (gr < M) v = *(const float4*)&X[(size_t)gr * 128 + k0 + c4];
            Xs[c4 + 0][r] = v.x; Xs[c4 + 1][r] = v.y;
            Xs[c4 + 2][r] = v.z; Xs[c4 + 3][r] = v.w;
        }
#pragma unroll
        for (int i = 0; i < 2; i++) {
            int k  = (tid >> 5) + i * 8;
            int c4 = (tid & 31) * 4;
            *(float4*)&Ws[k][c4] = *(const float4*)&W[(size_t)(k0 + k) * 128 + c4];
        }
        __syncthreads();
#pragma unroll
        for (int k = 0; k < GBK; k++) {
            float a[8], b[8];
            *(float4*)(a)     = *(float4*)&Xs[k][ty * 8];
            *(float4*)(a + 4) = *(float4*)&Xs[k][ty * 8 + 4];
            *(float4*)(b)     = *(float4*)&Ws[k][tx * 8];
            *(float4*)(b + 4) = *(float4*)&Ws[k][tx * 8 + 4];
#pragma unroll
            for (int i = 0; i < 8; i++)
#pragma unroll
                for (int j = 0; j < 8; j++) acc[i][j] = fmaf(a[i], b[j], acc[i][j]);
        }
        __syncthreads();
    }
#pragma unroll
    for (int i = 0; i < 8; i++) {
        int gr = rowBase + ty * 8 + i;
        if (gr < M) {
#pragma unroll
            for (int j = 0; j < 8; j += 4) {
                float4 v;
                v.x = acc[i][j + 0]; v.y = acc[i][j + 1];
                v.z = acc[i][j + 2]; v.w = acc[i][j + 3];
                *(float4*)&out[(size_t)gr * 128 + tx * 8 + j] = v;
            }
        }
    }
}

// ---------------- per-node attention logits e_src/e_dst ----------------------
__device__ __forceinline__ float warp_sum(float v) {
#pragma unroll
    for (int o = 16; o; o >>= 1) v += __shfl_xor_sync(0xffffffffu, v, o);
    return v;
}

__global__ void compute_e_kernel(const float* __restrict__ h,
                                 const float* __restrict__ asrc,
                                 const float* __restrict__ adst,
                                 float* __restrict__ es, float* __restrict__ ed,
                                 int n) {
    int w = (blockIdx.x * blockDim.x + threadIdx.x) >> 5;
    int lane = threadIdx.x & 31;
    if (w >= n) return;
    const float* hp = h + (size_t)w * 128;
    float v0 = hp[lane], v1 = hp[32 + lane], v2 = hp[64 + lane], v3 = hp[96 + lane];
    float s0 = warp_sum(v0 * __ldg(&asrc[lane]));
    float s1 = warp_sum(v1 * __ldg(&asrc[32 + lane]));
    float s2 = warp_sum(v2 * __ldg(&asrc[64 + lane]));
    float s3 = warp_sum(v3 * __ldg(&asrc[96 + lane]));
    float d0 = warp_sum(v0 * __ldg(&adst[lane]));
    float d1 = warp_sum(v1 * __ldg(&adst[32 + lane]));
    float d2 = warp_sum(v2 * __ldg(&adst[64 + lane]));
    float d3 = warp_sum(v3 * __ldg(&adst[96 + lane]));
    if (lane == 0) {
        *(float4*)&es[w * 4] = make_float4(s0, s1, s2, s3);
        *(float4*)&ed[w * 4] = make_float4(d0, d1, d2, d3);
    }
}

// ---------------- aggregation: one warp per destination node -----------------
__device__ __forceinline__ float lrelu(float x) {
    return x > 0.f ? x : NEG_SLOPE * x;
}

// mode 0: out = relu(agg + bias); mode 1: out = log_softmax(agg + bias)
__global__ __launch_bounds__(256)
void aggregate_kernel(const float* __restrict__ h, const float* __restrict__ es,
                      const float* __restrict__ ed, const float* __restrict__ bias,
                      float* __restrict__ out, int n, int mode) {
    int w = blockIdx.x * (blockDim.x >> 5) + (threadIdx.x >> 5);
    int lane = threadIdx.x & 31;
    if (w >= n) return;
    int beg = g_off[w], end = g_off[w + 1];
    float4 edv = *(const float4*)&ed[w * 4];

    // Pass 1: online softmax (max + scaled sum), per head
    float m0 = -1e30f, m1 = -1e30f, m2 = -1e30f, m3 = -1e30f;
    float z0 = 0.f, z1 = 0.f, z2 = 0.f, z3 = 0.f;
    for (int j = beg + lane; j < end; j += 32) {
        int s = g_csr[j];
        float4 e = *(const float4*)&es[s * 4];
        float c0 = lrelu(e.x + edv.x), c1 = lrelu(e.y + edv.y);
        float c2 = lrelu(e.z + edv.z), c3 = lrelu(e.w + edv.w);
        float nm;
        nm = fmaxf(m0, c0); z0 = z0 * __expf(m0 - nm) + __expf(c0 - nm); m0 = nm;
        nm = fmaxf(m1, c1); z1 = z1 * __expf(m1 - nm) + __expf(c1 - nm); m1 = nm;
        nm = fmaxf(m2, c2); z2 = z2 * __expf(m2 - nm) + __expf(c2 - nm); m2 = nm;
        nm = fmaxf(m3, c3); z3 = z3 * __expf(m3 - nm) + __expf(c3 - nm); m3 = nm;
    }
#pragma unroll
    for (int o = 16; o; o >>= 1) {
        float om, oz, nm;
        om = __shfl_xor_sync(0xffffffffu, m0, o); oz = __shfl_xor_sync(0xffffffffu, z0, o);
        nm = fmaxf(m0, om); z0 = z0 * __expf(m0 - nm) + oz * __expf(om - nm); m0 = nm;
        om = __shfl_xor_sync(0xffffffffu, m1, o); oz = __shfl_xor_sync(0xffffffffu, z1, o);
        nm = fmaxf(m1, om); z1 = z1 * __expf(m1 - nm) + oz * __expf(om - nm); m1 = nm;
        om = __shfl_xor_sync(0xffffffffu, m2, o); oz = __shfl_xor_sync(0xffffffffu, z2, o);
        nm = fmaxf(m2, om); z2 = z2 * __expf(m2 - nm) + oz * __expf(om - nm); m2 = nm;
        om = __shfl_xor_sync(0xffffffffu, m3, o); oz = __shfl_xor_sync(0xffffffffu, z3, o);
        nm = fmaxf(m3, om); z3 = z3 * __expf(m3 - nm) + oz * __expf(om - nm); m3 = nm;
    }
    float i0 = (z0 > 0.f) ? 1.f / z0 : 0.f;
    float i1 = (z1 > 0.f) ? 1.f / z1 : 0.f;
    float i2 = (z2 > 0.f) ? 1.f / z2 : 0.f;
    float i3 = (z3 > 0.f) ? 1.f / z3 : 0.f;

    // Pass 2: weighted accumulate of h[src]; lane owns feature (head, lane)
    float acc0 = 0.f, acc1 = 0.f, acc2 = 0.f, acc3 = 0.f;
    for (int j0 = beg; j0 < end; j0 += 32) {
        int j = j0 + lane;
        int s = 0;
        float a0 = 0.f, a1 = 0.f, a2 = 0.f, a3 = 0.f;
        if (j < end) {
            s = g_csr[j];
            float4 e = *(const float4*)&es[s * 4];
            a0 = __expf(lrelu(e.x + edv.x) - m0) * i0;
            a1 = __expf(lrelu(e.y + edv.y) - m1) * i1;
            a2 = __expf(lrelu(e.z + edv.z) - m2) * i2;
            a3 = __expf(lrelu(e.w + edv.w) - m3) * i3;
        }
        int cnt = min(32, end - j0);
        for (int k = 0; k < cnt; k++) {
            int   sk = __shfl_sync(0xffffffffu, s, k);
            float b0 = __shfl_sync(0xffffffffu, a0, k);
            float b1 = __shfl_sync(0xffffffffu, a1, k);
            float b2 = __shfl_sync(0xffffffffu, a2, k);
            float b3 = __shfl_sync(0xffffffffu, a3, k);
            const float* hp = h + (size_t)sk * 128;
            acc0 = fmaf(b0, __ldg(hp + lane),      acc0);
            acc1 = fmaf(b1, __ldg(hp + 32 + lane), acc1);
            acc2 = fmaf(b2, __ldg(hp + 64 + lane), acc2);
            acc3 = fmaf(b3, __ldg(hp + 96 + lane), acc3);
        }
    }
    acc0 += __ldg(&bias[lane]);
    acc1 += __ldg(&bias[32 + lane]);
    acc2 += __ldg(&bias[64 + lane]);
    acc3 += __ldg(&bias[96 + lane]);

    float* op = out + (size_t)w * 128;
    if (mode == 0) {
        op[lane]      = fmaxf(acc0, 0.f);
        op[32 + lane] = fmaxf(acc1, 0.f);
        op[64 + lane] = fmaxf(acc2, 0.f);
        op[96 + lane] = fmaxf(acc3, 0.f);
    } else {
        float mx = fmaxf(fmaxf(acc0, acc1), fmaxf(acc2, acc3));
#pragma unroll
        for (int o = 16; o; o >>= 1) mx = fmaxf(mx, __shfl_xor_sync(0xffffffffu, mx, o));
        float se = __expf(acc0 - mx) + __expf(acc1 - mx) + __expf(acc2 - mx) + __expf(acc3 - mx);
        se = warp_sum(se);
        float lse = mx + logf(se);
        op[lane]      = acc0 - lse;
        op[32 + lane] = acc1 - lse;
        op[64 + lane] = acc2 - lse;
        op[96 + lane] = acc3 - lse;
    }
}

// ---------------- launch -----------------------------------------------------
extern "C" void kernel_launch(void* const* d_in, const int* in_sizes, int n_in,
                              void* d_out, int out_size) {
    const int*   edge  = (const int*)d_in[0];     // [2, E]
    const float* feats = (const float*)d_in[1];   // [N, 128]
    const float* W1    = (const float*)d_in[2];
    const float* a1s   = (const float*)d_in[3];
    const float* a1d   = (const float*)d_in[4];
    const float* b1    = (const float*)d_in[5];
    const float* W2    = (const float*)d_in[6];
    const float* a2s   = (const float*)d_in[7];
    const float* a2d   = (const float*)d_in[8];
    const float* b2    = (const float*)d_in[9];
    float* out = (float*)d_out;

    const int E = in_sizes[0] / 2;
    const int N = in_sizes[1] / DFEAT;
    const int* src = edge;
    const int* dst = edge + E;

    // resolve device-global addresses for kernels that take them as params
    float *bufA, *bufB, *es, *ed;
    cudaGetSymbolAddress((void**)&bufA, g_bufA);
    cudaGetSymbolAddress((void**)&bufB, g_bufB);
    cudaGetSymbolAddress((void**)&es, g_es);
    cudaGetSymbolAddress((void**)&ed, g_ed);

    const int nbScan = (N + 1023) / 1024;

    // CSR build
    zero_kernel<<<(N + 255) / 256, 256>>>(N);
    count_kernel<<<(E + 255) / 256, 256>>>(dst, E);
    scan1_kernel<<<nbScan, 1024>>>(N);
    scan2_kernel<<<1, 128>>>(nbScan);
    scan3_kernel<<<nbScan, 1024>>>(N, E);
    scatter_kernel<<<(E + 255) / 256, 256>>>(src, dst, E);

    const int gemmGrid = (N + GBM - 1) / GBM;
    const int eGrid    = (N * 32 + 255) / 256;
    const int aggGrid  = (N + 7) / 8;

    // Layer 1
    gemm128_kernel<<<gemmGrid, 256>>>(feats, W1, bufA, N);
    compute_e_kernel<<<eGrid, 256>>>(bufA, a1s, a1d, es, ed, N);
    aggregate_kernel<<<aggGrid, 256>>>(bufA, es, ed, b1, bufB, N, 0);

    // Layer 2
    gemm128_kernel<<<gemmGrid, 256>>>(bufB, W2, bufA, N);
    compute_e_kernel<<<eGrid, 256>>>(bufA, a2s, a2d, es, ed, N);
    aggregate_kernel<<<aggGrid, 256>>>(bufA, es, ed, b2, out, N, 1);
}